// round 17
// baseline (speedup 1.0000x reference)
#include <cuda_runtime.h>
#include <cuda_bf16.h>
#include <math.h>
#include <stdint.h>

// Problem constants (fixed shapes)
#define BB 4
#define HH 64
#define WW 64
#define FF 256
#define CC 19
#define SS 256
#define TWOS (2*SS)            // 512
#define NN (BB*HH*WW)          // 16384 pixels
#define MM (CC*TWOS)           // 9728 memory vectors
#define MTILES (MM/128)        // 76 m-tiles per strip
#define NSTRIPS (NN/128)       // 128 strips

// Scratch (static device globals; no allocation at runtime)
__device__ __nv_bfloat16 g_A[NN * FF];   // normalized feats, [n][f] row-major (8 MB)
__device__ __nv_bfloat16 g_Bm[MM * FF];  // normalized memory, [m][f] row-major (5 MB)
__device__ float g_total[NN];            // per-pixel sum of exp(cos/temp)
__device__ float g_blocksum[NN];         // per-pixel own-block sum of exp
__device__ float g_owncos[NN * SS];      // per-pixel SELECTED-half cos (16.8 MB)
__device__ float g_contrib[CC];          // per-class contribution accumulator
__device__ int   g_cnt[CC];              // per-class masked-pixel count
__device__ int   g_strip_cnt[NSTRIPS];   // per-strip m-tile arrival counters
__device__ int   g_done;                 // completed-strip counter

// ---------------------------------------------------------------------------
// exp(2*c) via MUFU: exp(2c) = 2^(2c*log2 e). ex2.approx rel err ~1e-6 here.
// ---------------------------------------------------------------------------
__device__ __forceinline__ float fexp2c(float c) {
    float y = c * 2.8853900817779268f;   // 2 * log2(e)
    float r;
    asm("ex2.approx.f32 %0, %1;" : "=f"(r) : "f"(y));
    return r;
}

__device__ __forceinline__ void cp16(uint32_t smem_dst, const void* gsrc) {
    asm volatile("cp.async.cg.shared.global [%0], [%1], 16;\n" :: "r"(smem_dst), "l"(gsrc));
}

__device__ __forceinline__ uint32_t smem_u32(const void* p) {
    uint32_t a;
    asm("{ .reg .u64 t; cvta.to.shared.u64 t, %1; cvt.u32.u64 %0, t; }" : "=r"(a) : "l"(p));
    return a;
}

__device__ __forceinline__ void ldm_x4(uint32_t* r, uint32_t addr) {
    asm volatile("ldmatrix.sync.aligned.m8n8.x4.shared.b16 {%0,%1,%2,%3}, [%4];"
        : "=r"(r[0]), "=r"(r[1]), "=r"(r[2]), "=r"(r[3]) : "r"(addr));
}

__device__ __forceinline__ void mma16816(float* d, const uint32_t* a, const uint32_t* b) {
    asm volatile(
        "mma.sync.aligned.m16n8k16.row.col.f32.bf16.bf16.f32 "
        "{%0,%1,%2,%3}, {%4,%5,%6,%7}, {%8,%9}, {%0,%1,%2,%3};\n"
        : "+f"(d[0]), "+f"(d[1]), "+f"(d[2]), "+f"(d[3])
        : "r"(a[0]), "r"(a[1]), "r"(a[2]), "r"(a[3]), "r"(b[0]), "r"(b[1]));
}

// ---------------------------------------------------------------------------
// K1: fused prep. Blocks [0,64): normalize feats (B,F,H,W) -> bf16 [n][f],
// zero totals. Blocks [64, 64+4864): normalize 2 memory rows each -> bf16.
// Blocks 64/65 also zero the class accumulators and arrival counters.
// ---------------------------------------------------------------------------
__global__ void k_prep(const float* __restrict__ pred,
                       const float* __restrict__ mem) {
    int blk = blockIdx.x;
    int t = threadIdx.x;

    if (blk < 64) {
        // ---- feats path: 256 threads = 4 rows of 64 pixels ----
        int w = t & 63;
        int h = (blk & 15) * 4 + (t >> 6);
        int b = blk >> 4;
        int n = (b * HH + h) * WW + w;
        const float* base = pred + (size_t)b * FF * HH * WW + h * WW + w;

        float sumsq = 0.0f;
        #pragma unroll 8
        for (int f = 0; f < FF; f++) {
            float v = base[f * (HH * WW)];
            sumsq += v * v;
        }
        float inv = rsqrtf(sumsq);

        for (int f0 = 0; f0 < FF; f0 += 8) {
            __nv_bfloat16 h8[8];
            #pragma unroll
            for (int j = 0; j < 8; j++)
                h8[j] = __float2bfloat16(base[(f0 + j) * (HH * WW)] * inv);
            *(uint4*)&g_A[(size_t)n * FF + f0] = *(const uint4*)h8;
        }
        g_total[n] = 0.0f;
        g_blocksum[n] = 0.0f;
    } else {
        // ---- memory path: 256 threads = 2 rows, 128 threads each ----
        __shared__ float red[8];
        int half = t >> 7;             // 0 or 1
        int tl = t & 127;
        int m = (blk - 64) * 2 + half;
        int wid = t >> 5;              // 0..7; warps 0-3 = row0, 4-7 = row1

        if (blk == 64 && t < CC) { g_contrib[t] = 0.0f; g_cnt[t] = 0; }
        if (blk == 65) {
            if (t < NSTRIPS) g_strip_cnt[t] = 0;
            if (t == NSTRIPS) g_done = 0;
        }

        float2 v = *(const float2*)&mem[(size_t)m * FF + 2 * tl];
        float p = v.x * v.x + v.y * v.y;
        #pragma unroll
        for (int o = 16; o > 0; o >>= 1) p += __shfl_down_sync(0xffffffffu, p, o);
        if ((t & 31) == 0) red[wid] = p;
        __syncthreads();
        float inv = rsqrtf(red[half * 4 + 0] + red[half * 4 + 1]
                         + red[half * 4 + 2] + red[half * 4 + 3]);
        __nv_bfloat162 o2;
        o2.x = __float2bfloat16(v.x * inv);
        o2.y = __float2bfloat16(v.y * inv);
        *(__nv_bfloat162*)&g_Bm[(size_t)m * FF + 2 * tl] = o2;
    }
}

// ---------------------------------------------------------------------------
// K2: bf16 HMMA GEMM. CTA tile 128 pix x 128 mem, 128 threads (4 warps,
// 2x2 grid), warp tile 64x64. BK=64, 3-stage cp.async pipeline, ldmatrix
// + XOR swizzle, register double-buffered fragments. 2 CTAs/SM.
// Epilogue: MUFU exp row sums + own-block sum + wm-selected cos scatter.
// Tail: last m-CTA per strip computes that strip's log-terms; overall-last
// CTA reduces the 19 class entries to the final scalar.
// ---------------------------------------------------------------------------
// Dynamic smem (bytes): labels[128]@0, rowsum@512, blksum@1024, hb[128]@1536,
// flags@2048, A stages @3072 (3 x 16KB), B stages @52224 (3 x 16KB).
#define SM_LAB   0
#define SM_PART  512
#define SM_BPART 1024
#define SM_HB    1536
#define SM_FLAG  2048
#define SM_A     3072
#define SM_B     (3072 + 3*16384)
#define SM_TOTAL (3072 + 6*16384)

__global__ __launch_bounds__(128, 2) void k_gemm(const int* __restrict__ labels,
                                                 const int* __restrict__ wm,
                                                 const unsigned char* __restrict__ mask,
                                                 float* __restrict__ out) {
    extern __shared__ __align__(1024) char dsm[];
    uint32_t sb = smem_u32(dsm);

    int tid = threadIdx.x;
    int m0 = blockIdx.x * 128;
    int n0 = blockIdx.y * 128;
    int wid = tid >> 5, lane = tid & 31;
    int wmw = wid & 1;          // pixel-dir warp (2): rows [wmw*64, +64)
    int wnw = wid >> 1;         // mem-dir warp (2): cols [wnw*64, +64)
    int g = lane >> 2, t4 = lane & 3;
    int l15 = lane & 15, l16 = lane >> 4;

    float* s_rowsum = (float*)(dsm + SM_PART);
    float* s_blksum = (float*)(dsm + SM_BPART);
    int*   s_lab    = (int*)(dsm + SM_LAB);
    int*   s_hb     = (int*)(dsm + SM_HB);
    int*   s_flag   = (int*)(dsm + SM_FLAG);

    s_rowsum[tid] = 0.0f;
    s_blksum[tid] = 0.0f;
    s_lab[tid] = labels[n0 + tid];
    s_hb[tid] = (wm[n0 + tid] == 1) ? 0 : 1;   // selected half index (0=first)

    float acc[4][8][4];
    #pragma unroll
    for (int mi = 0; mi < 4; mi++)
        #pragma unroll
        for (int ni = 0; ni < 8; ni++)
            #pragma unroll
            for (int q = 0; q < 4; q++) acc[mi][ni][q] = 0.0f;

    // Fill one BK=64 stage: A 1024 + B 1024 16B-chunks over 128 threads.
#define ISSUE(IT, BUF) do {                                                     \
        int k0_ = (IT) * 64;                                                    \
        _Pragma("unroll")                                                       \
        for (int r_ = 0; r_ < 8; r_++) {                                        \
            int id = tid + r_ * 128;          /* 0..1023 */                     \
            int row = id >> 3, c = id & 7;                                      \
            int sw = (c ^ (row & 7)) << 4;                                      \
            cp16(sb + SM_A + (BUF) * 16384 + row * 128 + sw,                    \
                 &g_A[(size_t)(n0 + row) * FF + k0_ + c * 8]);                  \
            cp16(sb + SM_B + (BUF) * 16384 + row * 128 + sw,                    \
                 &g_Bm[(size_t)(m0 + row) * FF + k0_ + c * 8]);                 \
        } } while (0)

    // Load the 8 fragments for k-chunk kc from stage buffers.
#define LOADFRAG(FA, FB, Ab, Bb, KC) do {                                       \
        _Pragma("unroll")                                                       \
        for (int mi_ = 0; mi_ < 4; mi_++) {                                     \
            int row = wmw * 64 + mi_ * 16 + l15;                                \
            ldm_x4(FA[mi_], (Ab) + row * 128 + (((KC) ^ (row & 7)) << 4));      \
        }                                                                       \
        _Pragma("unroll")                                                       \
        for (int nj_ = 0; nj_ < 4; nj_++) {                                     \
            int row = wnw * 64 + nj_ * 16 + l15;                                \
            ldm_x4(FB[nj_], (Bb) + row * 128 + (((KC) ^ (row & 7)) << 4));      \
        } } while (0)

#define DOMMA(FA, FB) do {                                                      \
        _Pragma("unroll")                                                       \
        for (int mi_ = 0; mi_ < 4; mi_++)                                       \
            _Pragma("unroll")                                                   \
            for (int nj_ = 0; nj_ < 4; nj_++) {                                 \
                uint32_t b0_[2] = { FB[nj_][0], FB[nj_][2] };                   \
                uint32_t b1_[2] = { FB[nj_][1], FB[nj_][3] };                   \
                mma16816(acc[mi_][2 * nj_],     FA[mi_], b0_);                  \
                mma16816(acc[mi_][2 * nj_ + 1], FA[mi_], b1_);                  \
            } } while (0)

    ISSUE(0, 0);
    asm volatile("cp.async.commit_group;\n");
    ISSUE(1, 1);
    asm volatile("cp.async.commit_group;\n");

    uint32_t fa[2][4][4], fb[2][4][4];

    #pragma unroll
    for (int it = 0; it < 4; it++) {
        if (it < 3) asm volatile("cp.async.wait_group 1;\n" ::: "memory");
        else        asm volatile("cp.async.wait_group 0;\n" ::: "memory");
        __syncthreads();
        if (it < 2) {
            ISSUE(it + 2, (it + 2) % 3);
            asm volatile("cp.async.commit_group;\n");
        }

        int buf = it % 3;
        uint32_t Ab = sb + SM_A + buf * 16384;
        uint32_t Bb = sb + SM_B + buf * 16384;

        // Register-double-buffered fragment pipeline over 4 k-chunks.
        LOADFRAG(fa[0], fb[0], Ab, Bb, (0 * 2 + l16));
        #pragma unroll
        for (int ks = 0; ks < 4; ks++) {
            int cur = ks & 1;
            if (ks < 3)
                LOADFRAG(fa[cur ^ 1], fb[cur ^ 1], Ab, Bb, ((ks + 1) * 2 + l16));
            DOMMA(fa[cur], fb[cur]);
        }
    }
#undef ISSUE
#undef LOADFRAG
#undef DOMMA
    __syncthreads();

    // Epilogue: MUFU exp + row sums + own-block sums + wm-selected cos
    // scatter. 128-aligned m-window lies in one 512-wide class block.
    int cls = m0 >> 9;
    int mbase = (m0 & 511) + wnw * 64;   // 64-aligned offset in class block
    int msel = mbase >> 8;               // which half this warp's cols fall in
    int moff = mbase & 255;              // offset within that half

    #pragma unroll
    for (int mi = 0; mi < 4; mi++) {
        int p0 = wmw * 64 + mi * 16 + g;
        int p1 = p0 + 8;
        bool own0 = (s_lab[p0] == cls);
        bool own1 = (s_lab[p1] == cls);
        bool sel0 = own0 && (s_hb[p0] == msel);
        bool sel1 = own1 && (s_hb[p1] == msel);
        float s0 = 0.0f, s1 = 0.0f;
        #pragma unroll
        for (int ni = 0; ni < 8; ni++) {
            float d0 = acc[mi][ni][0], d1 = acc[mi][ni][1];
            float d2 = acc[mi][ni][2], d3 = acc[mi][ni][3];
            s0 += fexp2c(d0) + fexp2c(d1);
            s1 += fexp2c(d2) + fexp2c(d3);
            int mo = moff + ni * 8 + t4 * 2;
            if (sel0) {
                float2 v; v.x = d0; v.y = d1;
                *(float2*)&g_owncos[(size_t)(n0 + p0) * SS + mo] = v;
            }
            if (sel1) {
                float2 v; v.x = d2; v.y = d3;
                *(float2*)&g_owncos[(size_t)(n0 + p1) * SS + mo] = v;
            }
        }
        s0 += __shfl_xor_sync(0xffffffffu, s0, 1);
        s0 += __shfl_xor_sync(0xffffffffu, s0, 2);
        s1 += __shfl_xor_sync(0xffffffffu, s1, 1);
        s1 += __shfl_xor_sync(0xffffffffu, s1, 2);
        if (t4 == 0) {
            atomicAdd(&s_rowsum[p0], s0);
            atomicAdd(&s_rowsum[p1], s1);
            if (own0) atomicAdd(&s_blksum[p0], s0);
            if (own1) atomicAdd(&s_blksum[p1], s1);
        }
    }
    __syncthreads();
    atomicAdd(&g_total[n0 + tid], s_rowsum[tid]);
    {
        float bsv = s_blksum[tid];
        if (bsv != 0.0f) atomicAdd(&g_blocksum[n0 + tid], bsv);
    }

    // ---- strip arrival: last m-CTA of this strip computes its log-terms ----
    __threadfence();
    if (tid == 0) {
        int old = atomicAdd(&g_strip_cnt[blockIdx.y], 1);
        s_flag[0] = (old == MTILES - 1) ? 1 : 0;
    }
    __syncthreads();
    if (s_flag[0]) {
        // terms for the 128 pixels of this strip: warp w handles pixels
        // w, w+4, ... ; lanes split the 256 selected cos values.
        for (int p = wid; p < 128; p += 4) {
            int n = n0 + p;
            if (!mask[n]) continue;
            float down = g_total[n] - g_blocksum[n];
            float ts = 0.0f;
            #pragma unroll
            for (int k = 0; k < 8; k++) {
                float c = g_owncos[(size_t)n * SS + lane + 32 * k];
                float pos = fexp2c(c);
                float r = pos / (pos + down + 1e-12f);
                ts += -logf(r + 1e-12f);
            }
            #pragma unroll
            for (int o = 16; o > 0; o >>= 1)
                ts += __shfl_xor_sync(0xffffffffu, ts, o);
            if (lane == 0) {
                atomicAdd(&g_contrib[s_lab[p]], ts);
                atomicAdd(&g_cnt[s_lab[p]], 1);
            }
        }
        // ---- overall-last strip computes the final scalar ----
        __threadfence();
        __syncthreads();
        if (tid == 0)
            s_flag[1] = (atomicAdd(&g_done, 1) == NSTRIPS - 1) ? 1 : 0;
        __syncthreads();
        if (s_flag[1] && wid == 0) {
            float loss = 0.0f, ccount = 0.0f;
            if (lane < CC) {
                int c = g_cnt[lane];
                if (c > 0) {
                    loss = g_contrib[lane] / ((float)c * (float)SS);
                    ccount = 1.0f;
                }
            }
            #pragma unroll
            for (int o = 16; o > 0; o >>= 1) {
                loss   += __shfl_xor_sync(0xffffffffu, loss, o);
                ccount += __shfl_xor_sync(0xffffffffu, ccount, o);
            }
            if (lane == 0) out[0] = loss / fmaxf(ccount, 1.0f);
        }
    }
}

// ---------------------------------------------------------------------------
extern "C" void kernel_launch(void* const* d_in, const int* in_sizes, int n_in,
                              void* d_out, int out_size) {
    const float*         mem    = (const float*)d_in[0];         // (19,512,256)
    const float*         pred   = (const float*)d_in[1];         // (4,256,64,64)
    const int*           labels = (const int*)d_in[2];           // (4,64,64)
    const unsigned char* mask   = (const unsigned char*)d_in[3]; // bool (1B)
    const int*           wm     = (const int*)d_in[4];           // (4,64,64)
    float*               out    = (float*)d_out;

    (void)in_sizes; (void)n_in; (void)out_size;

    cudaFuncSetAttribute(k_gemm, cudaFuncAttributeMaxDynamicSharedMemorySize, SM_TOTAL);

    k_prep<<<64 + MM / 2, 256>>>(pred, mem);
    k_gemm<<<dim3(MM / 128, NN / 128), 128, SM_TOTAL>>>(labels, wm, mask, out);
}